// round 15
// baseline (speedup 1.0000x reference)
#include <cuda_runtime.h>
#include <cstdint>
#include <cstddef>

// CosAttn2d fused: B=32, C=512, H=W=32, n_head=8, M=48
// One block per bh. Phase 1: ctx[k'=r*64+d][e] = sum_n coef_r[n]*ka[d,n]*v[e,n]
// (col 64 = ksum) accumulated in registers, stored to SMEM.
// Phase 2: out[e,n] = (sum_k' coef*qa*ctx[k'][e]) / (sum_k' coef*qa*ksum[k'])
// reading ctx from SMEM (uniform broadcast), packed f32x2 math throughout.

#define HW      1024
#define DH      64
#define NBH     256
#define FREQ    0.0327249234748937f   // pi/96
#define DNORM   0.2102241038134286f   // 512^-0.25
#define EPS     1e-5f
#define CTX_LD  68                    // floats per ctx row (16B-aligned rows)

typedef unsigned long long ull;

// ---- dynamic smem layout ----
// [0, 69632)            : ctx_s[256][68]  (float)
// [69632, 103424)       : union { ks_t[64][66] + vs_t[64][66] (float) | qs2[64][66] (ull) }
// [103424, 104448)      : cs[4][64] (float)
#define SMEM_CTX_BYTES   (256 * CTX_LD * 4)
#define SMEM_TILE_BYTES  (64 * 66 * 8)
#define SMEM_BYTES       (SMEM_CTX_BYTES + SMEM_TILE_BYTES + 4 * 64 * 4)

__device__ __forceinline__ ull pk2(float lo, float hi) {
    ull r; asm("mov.b64 %0, {%1, %2};" : "=l"(r) : "f"(lo), "f"(hi)); return r;
}
__device__ __forceinline__ void upk2(ull v, float& lo, float& hi) {
    asm("mov.b64 {%0, %1}, %2;" : "=f"(lo), "=f"(hi) : "l"(v));
}
__device__ __forceinline__ ull mul2(ull a, ull b) {
    ull r; asm("mul.rn.f32x2 %0, %1, %2;" : "=l"(r) : "l"(a), "l"(b)); return r;
}
__device__ __forceinline__ ull add2(ull a, ull b) {
    ull r; asm("add.rn.f32x2 %0, %1, %2;" : "=l"(r) : "l"(a), "l"(b)); return r;
}
__device__ __forceinline__ void fma2(ull& d, ull a, ull b) {
    asm("fma.rn.f32x2 %0, %1, %2, %3;" : "=l"(d) : "l"(a), "l"(b), "l"(d));
}

__global__ __launch_bounds__(256, 2)
void fused_kernel(const float* __restrict__ Q, const float* __restrict__ K,
                  const float* __restrict__ V, float* __restrict__ O) {
    extern __shared__ char smem_raw[];
    float (*ctx_s)[CTX_LD] = (float(*)[CTX_LD])smem_raw;
    float (*ks_t)[66] = (float(*)[66])(smem_raw + SMEM_CTX_BYTES);
    float (*vs_t)[66] = (float(*)[66])(smem_raw + SMEM_CTX_BYTES + 64 * 66 * 4);
    ull   (*qs2)[66]  = (ull(*)[66])(smem_raw + SMEM_CTX_BYTES);
    float (*cs)[64]   = (float(*)[64])(smem_raw + SMEM_CTX_BYTES + SMEM_TILE_BYTES);

    const int bh = blockIdx.x;
    const int t  = threadIdx.x;
    const float* qb = Q + (size_t)bh * (DH * HW);
    const float* kb = K + (size_t)bh * (DH * HW);
    const float* vb = V + (size_t)bh * (DH * HW);
    float*       ob = O + (size_t)bh * (DH * HW);

    // ================= Phase 1: ctx = K'^T V =================
    {
        const int ty = t >> 3;           // 0..31
        const int tx = t & 7;            // 0..7  (e = tx + 8i)
        const int r  = ty >> 3;          // 0..3  (uniform per warp)
        const int dl = ty & 7;           // d-pairs {2dl+16jp, +1}

        ull acc2[4][8];
        ull ksa2[4];
#pragma unroll
        for (int jp = 0; jp < 4; jp++) {
            ksa2[jp] = 0ull;
#pragma unroll
            for (int i = 0; i < 8; i++) acc2[jp][i] = 0ull;
        }

        const int lr = t >> 4;           // 0..15 (gmem row base)
        const int lc = (t & 15) << 2;    // 0..60 (n col)

        for (int chunk = 0; chunk < 16; chunk++) {
            const int n0 = chunk << 6;
            __syncthreads();
#pragma unroll
            for (int it = 0; it < 4; it++) {
                const int row = lr + (it << 4);
                float4 kv = *(const float4*)(kb + row * HW + n0 + lc);
                ks_t[lc + 0][row] = fmaxf(kv.x * DNORM, 0.f) + EPS;
                ks_t[lc + 1][row] = fmaxf(kv.y * DNORM, 0.f) + EPS;
                ks_t[lc + 2][row] = fmaxf(kv.z * DNORM, 0.f) + EPS;
                ks_t[lc + 3][row] = fmaxf(kv.w * DNORM, 0.f) + EPS;
                float4 vv = *(const float4*)(vb + row * HW + n0 + lc);
                vs_t[lc + 0][row] = vv.x;
                vs_t[lc + 1][row] = vv.y;
                vs_t[lc + 2][row] = vv.z;
                vs_t[lc + 3][row] = vv.w;
            }
            if (t < 64) {
                const int n = n0 + t;
                float ch, sh, cw, sw;
                __sincosf((float)(n >> 5) * FREQ, &sh, &ch);
                __sincosf((float)(n & 31) * FREQ, &sw, &cw);
                cs[0][t] = ch * cw;
                cs[1][t] = ch * sw;
                cs[2][t] = sh * cw;
                cs[3][t] = sh * sw;
            }
            __syncthreads();

#pragma unroll 2
            for (int n = 0; n < 64; n++) {
                const float cfv = cs[r][n];
                const ull cf2 = pk2(cfv, cfv);
                const ull* ksp = (const ull*)&ks_t[n][0];
                ull ksc[4];
#pragma unroll
                for (int jp = 0; jp < 4; jp++) {
                    ull k2 = ksp[dl + (jp << 3)];
                    ksc[jp] = mul2(k2, cf2);
                    ksa2[jp] = add2(ksa2[jp], ksc[jp]);
                }
                ull bvd[8];
#pragma unroll
                for (int i = 0; i < 8; i++) {
                    float b = vs_t[n][tx + (i << 3)];
                    bvd[i] = pk2(b, b);
                }
#pragma unroll
                for (int jp = 0; jp < 4; jp++)
#pragma unroll
                    for (int i = 0; i < 8; i++)
                        fma2(acc2[jp][i], ksc[jp], bvd[i]);
            }
        }

        // write ctx to smem (ctx region untouched by tiles; no sync needed yet)
#pragma unroll
        for (int jp = 0; jp < 4; jp++) {
            const int d0 = (dl << 1) + (jp << 4);
            float* r0 = &ctx_s[(r << 6) + d0][0];
            float* r1 = r0 + CTX_LD;
#pragma unroll
            for (int i = 0; i < 8; i++) {
                float a, b;
                upk2(acc2[jp][i], a, b);
                r0[tx + (i << 3)] = a;
                r1[tx + (i << 3)] = b;
            }
            if (tx == 0) {
                float a, b;
                upk2(ksa2[jp], a, b);
                r0[64] = a;
                r1[64] = b;
            }
        }
    }

    // ================= Phase 2: out = (Q' ctx) / D =================
    {
        const int te = t >> 5;            // 0..7 : e = te*8 + i (warp-uniform)
        const int tn = t & 31;            // n = n0 + tn*4 + jj

        for (int chunk = 0; chunk < 8; chunk++) {
            const int n0 = chunk << 7;
            __syncthreads();              // ctx ready (chunk 0) / prior qs2 reads done
#pragma unroll
            for (int it = 0; it < 8; it++) {
                const int row = te + (it << 3);
                float4 qv = *(const float4*)(qb + row * HW + n0 + (tn << 2));
                float4 s;
                s.x = fmaxf(qv.x * DNORM, 0.f) + EPS;
                s.y = fmaxf(qv.y * DNORM, 0.f) + EPS;
                s.z = fmaxf(qv.z * DNORM, 0.f) + EPS;
                s.w = fmaxf(qv.w * DNORM, 0.f) + EPS;
                *(float4*)((char*)&qs2[row][0] + (tn << 4)) = s;
            }
            __syncthreads();

            ull cf2a[4], cf2b[4];
            {
                float cf[4][4];
#pragma unroll
                for (int jj = 0; jj < 4; jj++) {
                    const int n = n0 + (tn << 2) + jj;
                    float ch, sh, cw, sw;
                    __sincosf((float)(n >> 5) * FREQ, &sh, &ch);
                    __sincosf((float)(n & 31) * FREQ, &sw, &cw);
                    cf[0][jj] = ch * cw;
                    cf[1][jj] = ch * sw;
                    cf[2][jj] = sh * cw;
                    cf[3][jj] = sh * sw;
                }
#pragma unroll
                for (int rr = 0; rr < 4; rr++) {
                    cf2a[rr] = pk2(cf[rr][0], cf[rr][1]);
                    cf2b[rr] = pk2(cf[rr][2], cf[rr][3]);
                }
            }

            ull acc2[8][2];
            ull Da0 = 0ull, Da1 = 0ull;
#pragma unroll
            for (int i = 0; i < 8; i++) { acc2[i][0] = 0ull; acc2[i][1] = 0ull; }

#pragma unroll
            for (int r = 0; r < 4; r++) {
                const float* crow = &ctx_s[r << 6][0];
#pragma unroll 4
                for (int d = 0; d < 64; d++) {
                    ulonglong2 q2 = *(const ulonglong2*)((const char*)&qs2[d][0] + (tn << 4));
                    const ull ap0 = mul2(q2.x, cf2a[r]);   // n jj=0,1
                    const ull ap1 = mul2(q2.y, cf2b[r]);   // n jj=2,3

                    const float4 cA = *(const float4*)(crow + (te << 3));      // uniform LDS
                    const float4 cB = *(const float4*)(crow + (te << 3) + 4);  // broadcast
                    const float ksv = crow[64];
                    const ull ksd = pk2(ksv, ksv);
                    fma2(Da0, ksd, ap0);
                    fma2(Da1, ksd, ap1);

                    const float cc[8] = {cA.x, cA.y, cA.z, cA.w, cB.x, cB.y, cB.z, cB.w};
#pragma unroll
                    for (int i = 0; i < 8; i++) {
                        const ull cd = pk2(cc[i], cc[i]);
                        fma2(acc2[i][0], cd, ap0);
                        fma2(acc2[i][1], cd, ap1);
                    }
                    crow += CTX_LD;
                }
            }

            float D0, D1, D2, D3;
            upk2(Da0, D0, D1);
            upk2(Da1, D2, D3);
            const float ri0 = 1.0f / D0, ri1 = 1.0f / D1;
            const float ri2 = 1.0f / D2, ri3 = 1.0f / D3;

#pragma unroll
            for (int i = 0; i < 8; i++) {
                float o0, o1, o2, o3;
                upk2(acc2[i][0], o0, o1);
                upk2(acc2[i][1], o2, o3);
                float4 o;
                o.x = o0 * ri0;
                o.y = o1 * ri1;
                o.z = o2 * ri2;
                o.w = o3 * ri3;
                *(float4*)(ob + (size_t)((te << 3) + i) * HW + n0 + (tn << 2)) = o;
            }
        }
    }
}

extern "C" void kernel_launch(void* const* d_in, const int* in_sizes, int n_in,
                              void* d_out, int out_size) {
    (void)in_sizes; (void)n_in; (void)out_size;
    const float* q = (const float*)d_in[0];
    const float* k = (const float*)d_in[1];
    const float* v = (const float*)d_in[2];
    float* o = (float*)d_out;

    cudaFuncSetAttribute(fused_kernel,
                         cudaFuncAttributeMaxDynamicSharedMemorySize, SMEM_BYTES);
    fused_kernel<<<NBH, 256, SMEM_BYTES>>>(q, k, v, o);
}

// round 16
// speedup vs baseline: 1.0002x; 1.0002x over previous
#include <cuda_runtime.h>
#include <cstdint>
#include <cstddef>

// CosAttn2d fused: B=32, C=512, H=W=32, n_head=8, M=48
// One block per bh. Phase 1: ctx[k'=r*64+d][e] = sum_n coef_r[n]*ka[d,n]*v[e,n]
// (col 64 = ksum) accumulated in registers, stored to SMEM.
// Phase 2: out[e,n] = (sum_k' coef*qa*ctx[k'][e]) / (sum_k' coef*qa*ksum[k'])
// reading ctx from SMEM (uniform broadcast), packed f32x2 math throughout.

#define HW      1024
#define DH      64
#define NBH     256
#define FREQ    0.0327249234748937f   // pi/96
#define DNORM   0.2102241038134286f   // 512^-0.25
#define EPS     1e-5f
#define CTX_LD  68                    // floats per ctx row (16B-aligned rows)

typedef unsigned long long ull;

// ---- dynamic smem layout ----
// [0, 69632)            : ctx_s[256][68]  (float)
// [69632, 103424)       : union { ks_t[64][66] + vs_t[64][66] (float) | qs2[64][66] (ull) }
// [103424, 104448)      : cs[4][64] (float)
#define SMEM_CTX_BYTES   (256 * CTX_LD * 4)
#define SMEM_TILE_BYTES  (64 * 66 * 8)
#define SMEM_BYTES       (SMEM_CTX_BYTES + SMEM_TILE_BYTES + 4 * 64 * 4)

__device__ __forceinline__ ull pk2(float lo, float hi) {
    ull r; asm("mov.b64 %0, {%1, %2};" : "=l"(r) : "f"(lo), "f"(hi)); return r;
}
__device__ __forceinline__ void upk2(ull v, float& lo, float& hi) {
    asm("mov.b64 {%0, %1}, %2;" : "=f"(lo), "=f"(hi) : "l"(v));
}
__device__ __forceinline__ ull mul2(ull a, ull b) {
    ull r; asm("mul.rn.f32x2 %0, %1, %2;" : "=l"(r) : "l"(a), "l"(b)); return r;
}
__device__ __forceinline__ ull add2(ull a, ull b) {
    ull r; asm("add.rn.f32x2 %0, %1, %2;" : "=l"(r) : "l"(a), "l"(b)); return r;
}
__device__ __forceinline__ void fma2(ull& d, ull a, ull b) {
    asm("fma.rn.f32x2 %0, %1, %2, %3;" : "=l"(d) : "l"(a), "l"(b), "l"(d));
}

__global__ __launch_bounds__(256, 2)
void fused_kernel(const float* __restrict__ Q, const float* __restrict__ K,
                  const float* __restrict__ V, float* __restrict__ O) {
    extern __shared__ char smem_raw[];
    float (*ctx_s)[CTX_LD] = (float(*)[CTX_LD])smem_raw;
    float (*ks_t)[66] = (float(*)[66])(smem_raw + SMEM_CTX_BYTES);
    float (*vs_t)[66] = (float(*)[66])(smem_raw + SMEM_CTX_BYTES + 64 * 66 * 4);
    ull   (*qs2)[66]  = (ull(*)[66])(smem_raw + SMEM_CTX_BYTES);
    float (*cs)[64]   = (float(*)[64])(smem_raw + SMEM_CTX_BYTES + SMEM_TILE_BYTES);

    const int bh = blockIdx.x;
    const int t  = threadIdx.x;
    const float* qb = Q + (size_t)bh * (DH * HW);
    const float* kb = K + (size_t)bh * (DH * HW);
    const float* vb = V + (size_t)bh * (DH * HW);
    float*       ob = O + (size_t)bh * (DH * HW);

    // ================= Phase 1: ctx = K'^T V =================
    {
        const int ty = t >> 3;           // 0..31
        const int tx = t & 7;            // 0..7  (e = tx + 8i)
        const int r  = ty >> 3;          // 0..3  (uniform per warp)
        const int dl = ty & 7;           // d-pairs {2dl+16jp, +1}

        ull acc2[4][8];
        ull ksa2[4];
#pragma unroll
        for (int jp = 0; jp < 4; jp++) {
            ksa2[jp] = 0ull;
#pragma unroll
            for (int i = 0; i < 8; i++) acc2[jp][i] = 0ull;
        }

        const int lr = t >> 4;           // 0..15 (gmem row base)
        const int lc = (t & 15) << 2;    // 0..60 (n col)

        for (int chunk = 0; chunk < 16; chunk++) {
            const int n0 = chunk << 6;
            __syncthreads();
#pragma unroll
            for (int it = 0; it < 4; it++) {
                const int row = lr + (it << 4);
                float4 kv = *(const float4*)(kb + row * HW + n0 + lc);
                ks_t[lc + 0][row] = fmaxf(kv.x * DNORM, 0.f) + EPS;
                ks_t[lc + 1][row] = fmaxf(kv.y * DNORM, 0.f) + EPS;
                ks_t[lc + 2][row] = fmaxf(kv.z * DNORM, 0.f) + EPS;
                ks_t[lc + 3][row] = fmaxf(kv.w * DNORM, 0.f) + EPS;
                float4 vv = *(const float4*)(vb + row * HW + n0 + lc);
                vs_t[lc + 0][row] = vv.x;
                vs_t[lc + 1][row] = vv.y;
                vs_t[lc + 2][row] = vv.z;
                vs_t[lc + 3][row] = vv.w;
            }
            if (t < 64) {
                const int n = n0 + t;
                float ch, sh, cw, sw;
                __sincosf((float)(n >> 5) * FREQ, &sh, &ch);
                __sincosf((float)(n & 31) * FREQ, &sw, &cw);
                cs[0][t] = ch * cw;
                cs[1][t] = ch * sw;
                cs[2][t] = sh * cw;
                cs[3][t] = sh * sw;
            }
            __syncthreads();

#pragma unroll 2
            for (int n = 0; n < 64; n++) {
                const float cfv = cs[r][n];
                const ull cf2 = pk2(cfv, cfv);
                const ull* ksp = (const ull*)&ks_t[n][0];
                ull ksc[4];
#pragma unroll
                for (int jp = 0; jp < 4; jp++) {
                    ull k2 = ksp[dl + (jp << 3)];
                    ksc[jp] = mul2(k2, cf2);
                    ksa2[jp] = add2(ksa2[jp], ksc[jp]);
                }
                ull bvd[8];
#pragma unroll
                for (int i = 0; i < 8; i++) {
                    float b = vs_t[n][tx + (i << 3)];
                    bvd[i] = pk2(b, b);
                }
#pragma unroll
                for (int jp = 0; jp < 4; jp++)
#pragma unroll
                    for (int i = 0; i < 8; i++)
                        fma2(acc2[jp][i], ksc[jp], bvd[i]);
            }
        }

        // write ctx to smem (ctx region untouched by tiles; no sync needed yet)
#pragma unroll
        for (int jp = 0; jp < 4; jp++) {
            const int d0 = (dl << 1) + (jp << 4);
            float* r0 = &ctx_s[(r << 6) + d0][0];
            float* r1 = r0 + CTX_LD;
#pragma unroll
            for (int i = 0; i < 8; i++) {
                float a, b;
                upk2(acc2[jp][i], a, b);
                r0[tx + (i << 3)] = a;
                r1[tx + (i << 3)] = b;
            }
            if (tx == 0) {
                float a, b;
                upk2(ksa2[jp], a, b);
                r0[64] = a;
                r1[64] = b;
            }
        }
    }

    // ================= Phase 2: out = (Q' ctx) / D =================
    {
        const int te = t >> 5;            // 0..7 : e = te*8 + i (warp-uniform)
        const int tn = t & 31;            // n = n0 + tn*4 + jj

        for (int chunk = 0; chunk < 8; chunk++) {
            const int n0 = chunk << 7;
            __syncthreads();              // ctx ready (chunk 0) / prior qs2 reads done
#pragma unroll
            for (int it = 0; it < 8; it++) {
                const int row = te + (it << 3);
                float4 qv = *(const float4*)(qb + row * HW + n0 + (tn << 2));
                float4 s;
                s.x = fmaxf(qv.x * DNORM, 0.f) + EPS;
                s.y = fmaxf(qv.y * DNORM, 0.f) + EPS;
                s.z = fmaxf(qv.z * DNORM, 0.f) + EPS;
                s.w = fmaxf(qv.w * DNORM, 0.f) + EPS;
                *(float4*)((char*)&qs2[row][0] + (tn << 4)) = s;
            }
            __syncthreads();

            ull cf2a[4], cf2b[4];
            {
                float cf[4][4];
#pragma unroll
                for (int jj = 0; jj < 4; jj++) {
                    const int n = n0 + (tn << 2) + jj;
                    float ch, sh, cw, sw;
                    __sincosf((float)(n >> 5) * FREQ, &sh, &ch);
                    __sincosf((float)(n & 31) * FREQ, &sw, &cw);
                    cf[0][jj] = ch * cw;
                    cf[1][jj] = ch * sw;
                    cf[2][jj] = sh * cw;
                    cf[3][jj] = sh * sw;
                }
#pragma unroll
                for (int rr = 0; rr < 4; rr++) {
                    cf2a[rr] = pk2(cf[rr][0], cf[rr][1]);
                    cf2b[rr] = pk2(cf[rr][2], cf[rr][3]);
                }
            }

            ull acc2[8][2];
            ull Da0 = 0ull, Da1 = 0ull;
#pragma unroll
            for (int i = 0; i < 8; i++) { acc2[i][0] = 0ull; acc2[i][1] = 0ull; }

#pragma unroll
            for (int r = 0; r < 4; r++) {
                const float* crow = &ctx_s[r << 6][0];
#pragma unroll 4
                for (int d = 0; d < 64; d++) {
                    ulonglong2 q2 = *(const ulonglong2*)((const char*)&qs2[d][0] + (tn << 4));
                    const ull ap0 = mul2(q2.x, cf2a[r]);   // n jj=0,1
                    const ull ap1 = mul2(q2.y, cf2b[r]);   // n jj=2,3

                    const float4 cA = *(const float4*)(crow + (te << 3));      // uniform LDS
                    const float4 cB = *(const float4*)(crow + (te << 3) + 4);  // broadcast
                    const float ksv = crow[64];
                    const ull ksd = pk2(ksv, ksv);
                    fma2(Da0, ksd, ap0);
                    fma2(Da1, ksd, ap1);

                    const float cc[8] = {cA.x, cA.y, cA.z, cA.w, cB.x, cB.y, cB.z, cB.w};
#pragma unroll
                    for (int i = 0; i < 8; i++) {
                        const ull cd = pk2(cc[i], cc[i]);
                        fma2(acc2[i][0], cd, ap0);
                        fma2(acc2[i][1], cd, ap1);
                    }
                    crow += CTX_LD;
                }
            }

            float D0, D1, D2, D3;
            upk2(Da0, D0, D1);
            upk2(Da1, D2, D3);
            const float ri0 = 1.0f / D0, ri1 = 1.0f / D1;
            const float ri2 = 1.0f / D2, ri3 = 1.0f / D3;

#pragma unroll
            for (int i = 0; i < 8; i++) {
                float o0, o1, o2, o3;
                upk2(acc2[i][0], o0, o1);
                upk2(acc2[i][1], o2, o3);
                float4 o;
                o.x = o0 * ri0;
                o.y = o1 * ri1;
                o.z = o2 * ri2;
                o.w = o3 * ri3;
                *(float4*)(ob + (size_t)((te << 3) + i) * HW + n0 + (tn << 2)) = o;
            }
        }
    }
}

extern "C" void kernel_launch(void* const* d_in, const int* in_sizes, int n_in,
                              void* d_out, int out_size) {
    (void)in_sizes; (void)n_in; (void)out_size;
    const float* q = (const float*)d_in[0];
    const float* k = (const float*)d_in[1];
    const float* v = (const float*)d_in[2];
    float* o = (float*)d_out;

    cudaFuncSetAttribute(fused_kernel,
                         cudaFuncAttributeMaxDynamicSharedMemorySize, SMEM_BYTES);
    fused_kernel<<<NBH, 256, SMEM_BYTES>>>(q, k, v, o);
}